// round 2
// baseline (speedup 1.0000x reference)
#include <cuda_runtime.h>
#include <math.h>

#define NB 4
#define TSEQ 2048
#define DM 512
#define NH 8
#define HD 64
#define NTOK (NB * TSEQ)      // 8192
#define C3 (3 * DM)           // 1536
#define ATT_SCALE 0.125f      // 1/sqrt(64)

// Scratch (no runtime allocation allowed)
__device__ float g_qkv[NTOK * C3];    // [n*T+t][3*512]  (q|k|v)
__device__ float g_attn[NTOK * DM];   // [n*T+t][h*64+d]

// ---------------------------------------------------------------------------
// Tiled SGEMM:  C[M,N] = A[M,K] * B[N,K]^T (+ bias), all row-major, K%16==0,
// M%128==0, N%128==0. 128x128 block tile, 8x8 per-thread microtile.
// ---------------------------------------------------------------------------
__global__ void __launch_bounds__(256, 2) sgemm_nt(
    const float* __restrict__ A, const float* __restrict__ B,
    float* __restrict__ C, const float* __restrict__ bias,
    int M, int N, int K)
{
    __shared__ float As[16][132];
    __shared__ float Bs[16][132];

    const int tid   = threadIdx.x;
    const int r0    = (tid >> 4) << 3;   // 0..120 step 8
    const int c0    = (tid & 15) << 3;
    const int mBase = blockIdx.y << 7;
    const int nBase = blockIdx.x << 7;

    const int ldRow = tid >> 2;          // 0..63
    const int ldK   = (tid & 3) << 2;    // 0,4,8,12

    float acc[8][8];
#pragma unroll
    for (int i = 0; i < 8; ++i)
#pragma unroll
        for (int j = 0; j < 8; ++j) acc[i][j] = 0.f;

    for (int k0 = 0; k0 < K; k0 += 16) {
        __syncthreads();
#pragma unroll
        for (int it = 0; it < 2; ++it) {
            int row = ldRow + it * 64;
            float4 a = *(const float4*)&A[(size_t)(mBase + row) * K + k0 + ldK];
            As[ldK + 0][row] = a.x; As[ldK + 1][row] = a.y;
            As[ldK + 2][row] = a.z; As[ldK + 3][row] = a.w;
            float4 b = *(const float4*)&B[(size_t)(nBase + row) * K + k0 + ldK];
            Bs[ldK + 0][row] = b.x; Bs[ldK + 1][row] = b.y;
            Bs[ldK + 2][row] = b.z; Bs[ldK + 3][row] = b.w;
        }
        __syncthreads();
#pragma unroll
        for (int kk = 0; kk < 16; ++kk) {
            float a[8], b[8];
            *(float4*)&a[0] = *(const float4*)&As[kk][r0];
            *(float4*)&a[4] = *(const float4*)&As[kk][r0 + 4];
            *(float4*)&b[0] = *(const float4*)&Bs[kk][c0];
            *(float4*)&b[4] = *(const float4*)&Bs[kk][c0 + 4];
#pragma unroll
            for (int i = 0; i < 8; ++i)
#pragma unroll
                for (int j = 0; j < 8; ++j)
                    acc[i][j] = fmaf(a[i], b[j], acc[i][j]);
        }
    }

    float bv[8];
#pragma unroll
    for (int j = 0; j < 8; ++j) bv[j] = bias ? bias[nBase + c0 + j] : 0.f;

#pragma unroll
    for (int i = 0; i < 8; ++i) {
        size_t off = (size_t)(mBase + r0 + i) * N + nBase + c0;
        float4 v0 = make_float4(acc[i][0] + bv[0], acc[i][1] + bv[1],
                                acc[i][2] + bv[2], acc[i][3] + bv[3]);
        float4 v1 = make_float4(acc[i][4] + bv[4], acc[i][5] + bv[5],
                                acc[i][6] + bv[6], acc[i][7] + bv[7]);
        *(float4*)&C[off]     = v0;
        *(float4*)&C[off + 4] = v1;
    }
}

// ---------------------------------------------------------------------------
// RoPE applied in-place to q (cols 0..511) and k (cols 512..1023) of g_qkv.
// One thread per (token, head, freq-pair i in 0..31).
// ---------------------------------------------------------------------------
__global__ void rope_kernel(float* __restrict__ qkv)
{
    int idx = blockIdx.x * blockDim.x + threadIdx.x;
    if (idx >= NTOK * NH * 32) return;
    int i  = idx & 31;
    int h  = (idx >> 5) & (NH - 1);
    int nt = idx >> 8;
    int t  = nt & (TSEQ - 1);

    // inv_freq = 10000^{-i/32}; compute in double for accuracy.
    float inv = (float)exp(-(double)i / 32.0 * 9.210340371976184);  // ln(1e4)
    float ang = (float)t * inv;
    float s, c;
    sincosf(ang, &s, &c);

    float* p = qkv + (size_t)nt * C3 + h * HD + i;
    float q1 = p[0], q2 = p[32];
    p[0]  = q1 * c - q2 * s;
    p[32] = q2 * c + q1 * s;
    float* pk = p + DM;
    float k1 = pk[0], k2 = pk[32];
    pk[0]  = k1 * c - k2 * s;
    pk[32] = k2 * c + k1 * s;
}

// ---------------------------------------------------------------------------
// Banded flash attention. Block = (q-tile of 64, head, batch), 256 threads
// as 16x16; each thread owns a 4x4 microtile. Online softmax across up to
// five 64-key chunks covering [q0-128, q0+192).
// ---------------------------------------------------------------------------
#define QT 64
#define KT 64
#define KPAD 65
#define ATTN_SMEM ((QT * HD + 3 * KT * KPAD) * 4)   // 66304 B

__global__ void __launch_bounds__(256, 2) attn_kernel(
    const float* __restrict__ qkv, float* __restrict__ out)
{
    extern __shared__ float sm[];
    float (*Qs)[HD]   = (float(*)[HD])sm;
    float (*Ks)[KPAD] = (float(*)[KPAD])(sm + QT * HD);
    float (*Vs)[KPAD] = (float(*)[KPAD])(sm + QT * HD + KT * KPAD);
    float (*Ps)[KPAD] = (float(*)[KPAD])(sm + QT * HD + 2 * KT * KPAD);

    const int tid = threadIdx.x;
    const int tx = tid & 15, ty = tid >> 4;
    const int qt = blockIdx.x, h = blockIdx.y, n = blockIdx.z;
    const int q0 = qt * QT;
    const int base = n * TSEQ * C3 + h * HD;

    // Load Q tile [64 x 64]
#pragma unroll
    for (int it = 0; it < 4; ++it) {
        int idx = tid + it * 256;
        int row = idx >> 4;
        int d4  = (idx & 15) << 2;
        *(float4*)&Qs[row][d4] =
            *(const float4*)&qkv[base + (q0 + row) * C3 + d4];
    }

    float m_i[4], l_i[4], o_acc[4][4];
#pragma unroll
    for (int i = 0; i < 4; ++i) {
        m_i[i] = -1e30f; l_i[i] = 0.f;
#pragma unroll
        for (int j = 0; j < 4; ++j) o_acc[i][j] = 0.f;
    }

    const int kv_begin = max(0, q0 - 128);
    const int kv_end   = min(TSEQ, q0 + QT + 128);
    __syncthreads();

    for (int kc = kv_begin; kc < kv_end; kc += KT) {
        // Load K,V chunk [64 x 64] (scalar smem stores to keep KPAD=65)
#pragma unroll
        for (int it = 0; it < 4; ++it) {
            int idx = tid + it * 256;
            int row = idx >> 4;
            int d4  = (idx & 15) << 2;
            int roff = base + (kc + row) * C3 + d4;
            float4 kvv = *(const float4*)&qkv[roff + DM];
            Ks[row][d4 + 0] = kvv.x; Ks[row][d4 + 1] = kvv.y;
            Ks[row][d4 + 2] = kvv.z; Ks[row][d4 + 3] = kvv.w;
            float4 vvv = *(const float4*)&qkv[roff + 2 * DM];
            Vs[row][d4 + 0] = vvv.x; Vs[row][d4 + 1] = vvv.y;
            Vs[row][d4 + 2] = vvv.z; Vs[row][d4 + 3] = vvv.w;
        }
        __syncthreads();

        // S = Q K^T (4x4 per thread)
        float s[4][4];
#pragma unroll
        for (int i = 0; i < 4; ++i)
#pragma unroll
            for (int j = 0; j < 4; ++j) s[i][j] = 0.f;

#pragma unroll 8
        for (int d = 0; d < HD; ++d) {
            float qv[4], kv[4];
#pragma unroll
            for (int i = 0; i < 4; ++i) qv[i] = Qs[ty * 4 + i][d];
#pragma unroll
            for (int j = 0; j < 4; ++j) kv[j] = Ks[tx * 4 + j][d];
#pragma unroll
            for (int i = 0; i < 4; ++i)
#pragma unroll
                for (int j = 0; j < 4; ++j)
                    s[i][j] = fmaf(qv[i], kv[j], s[i][j]);
        }

        // Mask + online softmax update (row group = 16 lanes of a half-warp)
#pragma unroll
        for (int i = 0; i < 4; ++i) {
            int qg = q0 + ty * 4 + i;
            float rowm = m_i[i];
            bool vld[4];
#pragma unroll
            for (int j = 0; j < 4; ++j) {
                int diff = kc + tx * 4 + j - qg;
                vld[j] = (diff >= -127) && (diff <= 128);
                s[i][j] = vld[j] ? s[i][j] * ATT_SCALE : -1e30f;
                rowm = fmaxf(rowm, s[i][j]);
            }
#pragma unroll
            for (int off = 8; off > 0; off >>= 1)
                rowm = fmaxf(rowm, __shfl_xor_sync(0xffffffffu, rowm, off));

            float scaleOld = __expf(m_i[i] - rowm);
            float lsum = 0.f;
#pragma unroll
            for (int j = 0; j < 4; ++j) {
                float p = vld[j] ? __expf(s[i][j] - rowm) : 0.f;
                Ps[ty * 4 + i][tx * 4 + j] = p;
                lsum += p;
            }
#pragma unroll
            for (int off = 8; off > 0; off >>= 1)
                lsum += __shfl_xor_sync(0xffffffffu, lsum, off);

            l_i[i] = l_i[i] * scaleOld + lsum;
            m_i[i] = rowm;
#pragma unroll
            for (int j = 0; j < 4; ++j) o_acc[i][j] *= scaleOld;
        }
        __syncthreads();

        // O += P V
#pragma unroll 8
        for (int kk = 0; kk < KT; ++kk) {
            float pv[4], vv[4];
#pragma unroll
            for (int i = 0; i < 4; ++i) pv[i] = Ps[ty * 4 + i][kk];
#pragma unroll
            for (int j = 0; j < 4; ++j) vv[j] = Vs[kk][tx * 4 + j];
#pragma unroll
            for (int i = 0; i < 4; ++i)
#pragma unroll
                for (int j = 0; j < 4; ++j)
                    o_acc[i][j] = fmaf(pv[i], vv[j], o_acc[i][j]);
        }
        __syncthreads();
    }

    // Write attn output: [n*T + q][h*64 + d]
#pragma unroll
    for (int i = 0; i < 4; ++i) {
        int q = q0 + ty * 4 + i;
        float invl = 1.f / l_i[i];
        float4 v = make_float4(o_acc[i][0] * invl, o_acc[i][1] * invl,
                               o_acc[i][2] * invl, o_acc[i][3] * invl);
        *(float4*)&out[(size_t)(n * TSEQ + q) * DM + h * HD + tx * 4] = v;
    }
}

// ---------------------------------------------------------------------------
extern "C" void kernel_launch(void* const* d_in, const int* in_sizes, int n_in,
                              void* d_out, int out_size)
{
    const float* x    = (const float*)d_in[0];   // [4,2048,512]
    const float* wqkv = (const float*)d_in[1];   // [1536,512]
    const float* outw = (const float*)d_in[2];   // [512,512]
    const float* outb = (const float*)d_in[3];   // [512]
    float* out = (float*)d_out;                  // [4,2048,512]

    void* qkv_p  = nullptr;
    void* attn_p = nullptr;
    cudaGetSymbolAddress(&qkv_p, g_qkv);
    cudaGetSymbolAddress(&attn_p, g_attn);
    float* qkv  = (float*)qkv_p;
    float* attn = (float*)attn_p;

    cudaFuncSetAttribute(attn_kernel,
                         cudaFuncAttributeMaxDynamicSharedMemorySize, ATTN_SMEM);

    // 1) QKV projection: [8192,1536] = x[8192,512] * Wqkv^T
    dim3 g1(C3 / 128, NTOK / 128);
    sgemm_nt<<<g1, 256>>>(x, wqkv, qkv, nullptr, NTOK, C3, DM);

    // 2) RoPE in place on q,k
    int rope_threads = NTOK * NH * 32;
    rope_kernel<<<(rope_threads + 255) / 256, 256>>>(qkv);

    // 3) Banded attention
    dim3 g3(TSEQ / QT, NH, NB);
    attn_kernel<<<g3, 256, ATTN_SMEM>>>(qkv, attn);

    // 4) Output projection + bias
    dim3 g4(DM / 128, NTOK / 128);
    sgemm_nt<<<g4, 256>>>(attn, outw, out, outb, NTOK, DM, DM);
}

// round 4
// speedup vs baseline: 1.5300x; 1.5300x over previous
#include <cuda_runtime.h>
#include <cuda_bf16.h>
#include <math.h>
#include <stdint.h>

#define NB 4
#define TSEQ 2048
#define DM 512
#define NH 8
#define HD 64
#define NTOK (NB * TSEQ)      // 8192
#define C3 (3 * DM)           // 1536
#define ATT_SCALE 0.125f

// Scratch (no runtime allocation allowed)
__device__ float g_qkv[NTOK * C3];
__device__ float g_attn[NTOK * DM];

// ---------------------------------------------------------------------------
// mma.sync helpers (base sm_1xx target — no 'a' features)
// ---------------------------------------------------------------------------
__device__ __forceinline__ uint32_t smem_u32(const void* p) {
    uint32_t a;
    asm("{ .reg .u64 t; cvta.to.shared.u64 t, %1; cvt.u32.u64 %0, t; }"
        : "=r"(a) : "l"(p));
    return a;
}

#define LDSM_X4(r0, r1, r2, r3, addr)                                      \
    asm volatile("ldmatrix.sync.aligned.m8n8.x4.shared.b16 "               \
                 "{%0,%1,%2,%3}, [%4];"                                    \
                 : "=r"(r0), "=r"(r1), "=r"(r2), "=r"(r3) : "r"(addr))

#define LDSM_X2(r0, r1, addr)                                              \
    asm volatile("ldmatrix.sync.aligned.m8n8.x2.shared.b16 "               \
                 "{%0,%1}, [%2];"                                          \
                 : "=r"(r0), "=r"(r1) : "r"(addr))

#define MMA_BF16(d, a, b)                                                  \
    asm volatile("mma.sync.aligned.m16n8k16.row.col.f32.bf16.bf16.f32 "    \
                 "{%0,%1,%2,%3}, {%4,%5,%6,%7}, {%8,%9}, {%0,%1,%2,%3};"   \
                 : "+f"((d)[0]), "+f"((d)[1]), "+f"((d)[2]), "+f"((d)[3])  \
                 : "r"((a)[0]), "r"((a)[1]), "r"((a)[2]), "r"((a)[3]),     \
                   "r"((b)[0]), "r"((b)[1]))

__device__ __forceinline__ uint32_t pack_hi(float x, float y) {
    __nv_bfloat162 t;
    t.x = __float2bfloat16(x);
    t.y = __float2bfloat16(y);
    return *reinterpret_cast<uint32_t*>(&t);
}
__device__ __forceinline__ uint32_t pack_lo(float x, float y) {
    __nv_bfloat162 t;
    t.x = __float2bfloat16(x - __bfloat162float(__float2bfloat16(x)));
    t.y = __float2bfloat16(y - __bfloat162float(__float2bfloat16(y)));
    return *reinterpret_cast<uint32_t*>(&t);
}

// ---------------------------------------------------------------------------
// HMMA GEMM: C[M,N] = A[M,K] * B[N,K]^T (+bias), fp32 in/out.
// bf16 hi/lo split, 3 MMA passes. Block tile 128x128, K-chunk 32.
// 8 warps as 2(m) x 4(n); warp tile 64x32 = 4x4 m16n8k16 fragments.
// ---------------------------------------------------------------------------
#define KC 32
#define LDP 40                      // padded smem row stride (bf16 elems)
#define LDPB (LDP * 2)              // row stride in bytes (80)

__global__ void __launch_bounds__(256) gemm_mma(
    const float* __restrict__ A, const float* __restrict__ B,
    float* __restrict__ C, const float* __restrict__ bias,
    int M, int N, int K)
{
    __shared__ __nv_bfloat16 Ah[128 * LDP], Al[128 * LDP];
    __shared__ __nv_bfloat16 Bh[128 * LDP], Bl[128 * LDP];

    const int tid  = threadIdx.x;
    const int wid  = tid >> 5;
    const int lane = tid & 31;
    const int wm   = wid >> 2;           // 0..1 -> m offset wm*64
    const int wn   = wid & 3;            // 0..3 -> n offset wn*32
    const int mBase = blockIdx.y << 7;
    const int nBase = blockIdx.x << 7;

    const uint32_t baseAh = smem_u32(Ah), baseAl = smem_u32(Al);
    const uint32_t baseBh = smem_u32(Bh), baseBl = smem_u32(Bl);

    // ldmatrix source addresses (per thread)
    // A (m16k16, x4): lanes 0-15 rows m0..15 @k0, lanes 16-31 same rows @k0+8
    const uint32_t aOff = (uint32_t)((wm * 64 + (lane & 15)) * LDPB
                                     + (lane >> 4) * 16);
    // B (k16n8, x2): lanes 0-7 rows n0..7 @k0, lanes 8-15 @k0+8 (mirrored 16-31)
    const uint32_t bOff = (uint32_t)((wn * 32 + (lane & 7)) * LDPB
                                     + ((lane >> 3) & 1) * 16);

    float acc[4][4][4];
#pragma unroll
    for (int i = 0; i < 4; ++i)
#pragma unroll
        for (int j = 0; j < 4; ++j)
#pragma unroll
            for (int r = 0; r < 4; ++r) acc[i][j][r] = 0.f;

    const int nchunk = K / KC;
    for (int ch = 0; ch < nchunk; ++ch) {
        const int k0 = ch * KC;
        __syncthreads();
        // Load + split chunk: 128 rows x 32 floats for A and B
#pragma unroll
        for (int it = 0; it < 4; ++it) {
            int idx = it * 256 + tid;
            int row = idx >> 3;
            int f4  = idx & 7;
            int so  = row * LDP + f4 * 4;
            float4 a = *(const float4*)&A[(size_t)(mBase + row) * K + k0 + f4 * 4];
            *(uint2*)&Ah[so] = make_uint2(pack_hi(a.x, a.y), pack_hi(a.z, a.w));
            *(uint2*)&Al[so] = make_uint2(pack_lo(a.x, a.y), pack_lo(a.z, a.w));
            float4 b = *(const float4*)&B[(size_t)(nBase + row) * K + k0 + f4 * 4];
            *(uint2*)&Bh[so] = make_uint2(pack_hi(b.x, b.y), pack_hi(b.z, b.w));
            *(uint2*)&Bl[so] = make_uint2(pack_lo(b.x, b.y), pack_lo(b.z, b.w));
        }
        __syncthreads();

#pragma unroll
        for (int ks = 0; ks < 2; ++ks) {
            const uint32_t kb = (uint32_t)(ks * 32);   // 16 bf16 = 32 B
            uint32_t ah[4][4], al[4][4], bh[4][2], bl[4][2];
#pragma unroll
            for (int mt = 0; mt < 4; ++mt) {
                uint32_t ad = aOff + (uint32_t)(mt * 16 * LDPB) + kb;
                LDSM_X4(ah[mt][0], ah[mt][1], ah[mt][2], ah[mt][3], baseAh + ad);
                LDSM_X4(al[mt][0], al[mt][1], al[mt][2], al[mt][3], baseAl + ad);
            }
#pragma unroll
            for (int nt = 0; nt < 4; ++nt) {
                uint32_t bd = bOff + (uint32_t)(nt * 8 * LDPB) + kb;
                LDSM_X2(bh[nt][0], bh[nt][1], baseBh + bd);
                LDSM_X2(bl[nt][0], bl[nt][1], baseBl + bd);
            }
#pragma unroll
            for (int mt = 0; mt < 4; ++mt)
#pragma unroll
                for (int nt = 0; nt < 4; ++nt) {
                    MMA_BF16(acc[mt][nt], ah[mt], bh[nt]);
                    MMA_BF16(acc[mt][nt], ah[mt], bl[nt]);
                    MMA_BF16(acc[mt][nt], al[mt], bh[nt]);
                }
        }
    }

    // Epilogue: fragment rows = t/4 (+8), cols = (t%4)*2 (+1)
    const int er = lane >> 2;
    const int ec = (lane & 3) << 1;
#pragma unroll
    for (int mt = 0; mt < 4; ++mt) {
#pragma unroll
        for (int nt = 0; nt < 4; ++nt) {
            int col = nBase + wn * 32 + nt * 8 + ec;
            float b0 = bias ? bias[col]     : 0.f;
            float b1 = bias ? bias[col + 1] : 0.f;
            int row0 = mBase + wm * 64 + mt * 16 + er;
            float2 v0 = make_float2(acc[mt][nt][0] + b0, acc[mt][nt][1] + b1);
            float2 v1 = make_float2(acc[mt][nt][2] + b0, acc[mt][nt][3] + b1);
            *(float2*)&C[(size_t)row0 * N + col]       = v0;
            *(float2*)&C[(size_t)(row0 + 8) * N + col] = v1;
        }
    }
}

// ---------------------------------------------------------------------------
// RoPE in-place on q,k of g_qkv
// ---------------------------------------------------------------------------
__global__ void rope_kernel(float* __restrict__ qkv)
{
    int idx = blockIdx.x * blockDim.x + threadIdx.x;
    if (idx >= NTOK * NH * 32) return;
    int i  = idx & 31;
    int h  = (idx >> 5) & (NH - 1);
    int nt = idx >> 8;
    int t  = nt & (TSEQ - 1);

    float inv = (float)exp(-(double)i / 32.0 * 9.210340371976184);
    float ang = (float)t * inv;
    float s, c;
    sincosf(ang, &s, &c);

    float* p = qkv + (size_t)nt * C3 + h * HD + i;
    float q1 = p[0], q2 = p[32];
    p[0]  = q1 * c - q2 * s;
    p[32] = q2 * c + q1 * s;
    float* pk = p + DM;
    float k1 = pk[0], k2 = pk[32];
    pk[0]  = k1 * c - k2 * s;
    pk[32] = k2 * c + k1 * s;
}

// ---------------------------------------------------------------------------
// Banded flash attention (unchanged from R2 passing version)
// ---------------------------------------------------------------------------
#define QT 64
#define KT 64
#define KPAD 65
#define ATTN_SMEM ((QT * HD + 3 * KT * KPAD) * 4)

__global__ void __launch_bounds__(256, 2) attn_kernel(
    const float* __restrict__ qkv, float* __restrict__ out)
{
    extern __shared__ float sm[];
    float (*Qs)[HD]   = (float(*)[HD])sm;
    float (*Ks)[KPAD] = (float(*)[KPAD])(sm + QT * HD);
    float (*Vs)[KPAD] = (float(*)[KPAD])(sm + QT * HD + KT * KPAD);
    float (*Ps)[KPAD] = (float(*)[KPAD])(sm + QT * HD + 2 * KT * KPAD);

    const int tid = threadIdx.x;
    const int tx = tid & 15, ty = tid >> 4;
    const int qt = blockIdx.x, h = blockIdx.y, n = blockIdx.z;
    const int q0 = qt * QT;
    const int base = n * TSEQ * C3 + h * HD;

#pragma unroll
    for (int it = 0; it < 4; ++it) {
        int idx = tid + it * 256;
        int row = idx >> 4;
        int d4  = (idx & 15) << 2;
        *(float4*)&Qs[row][d4] =
            *(const float4*)&qkv[base + (q0 + row) * C3 + d4];
    }

    float m_i[4], l_i[4], o_acc[4][4];
#pragma unroll
    for (int i = 0; i < 4; ++i) {
        m_i[i] = -1e30f; l_i[i] = 0.f;
#pragma unroll
        for (int j = 0; j < 4; ++j) o_acc[i][j] = 0.f;
    }

    const int kv_begin = max(0, q0 - 128);
    const int kv_end   = min(TSEQ, q0 + QT + 128);
    __syncthreads();

    for (int kc = kv_begin; kc < kv_end; kc += KT) {
#pragma unroll
        for (int it = 0; it < 4; ++it) {
            int idx = tid + it * 256;
            int row = idx >> 4;
            int d4  = (idx & 15) << 2;
            int roff = base + (kc + row) * C3 + d4;
            float4 kvv = *(const float4*)&qkv[roff + DM];
            Ks[row][d4 + 0] = kvv.x; Ks[row][d4 + 1] = kvv.y;
            Ks[row][d4 + 2] = kvv.z; Ks[row][d4 + 3] = kvv.w;
            float4 vvv = *(const float4*)&qkv[roff + 2 * DM];
            Vs[row][d4 + 0] = vvv.x; Vs[row][d4 + 1] = vvv.y;
            Vs[row][d4 + 2] = vvv.z; Vs[row][d4 + 3] = vvv.w;
        }
        __syncthreads();

        float s[4][4];
#pragma unroll
        for (int i = 0; i < 4; ++i)
#pragma unroll
            for (int j = 0; j < 4; ++j) s[i][j] = 0.f;

#pragma unroll 8
        for (int d = 0; d < HD; ++d) {
            float qv[4], kv[4];
#pragma unroll
            for (int i = 0; i < 4; ++i) qv[i] = Qs[ty * 4 + i][d];
#pragma unroll
            for (int j = 0; j < 4; ++j) kv[j] = Ks[tx * 4 + j][d];
#pragma unroll
            for (int i = 0; i < 4; ++i)
#pragma unroll
                for (int j = 0; j < 4; ++j)
                    s[i][j] = fmaf(qv[i], kv[j], s[i][j]);
        }

#pragma unroll
        for (int i = 0; i < 4; ++i) {
            int qg = q0 + ty * 4 + i;
            float rowm = m_i[i];
            bool vld[4];
#pragma unroll
            for (int j = 0; j < 4; ++j) {
                int diff = kc + tx * 4 + j - qg;
                vld[j] = (diff >= -127) && (diff <= 128);
                s[i][j] = vld[j] ? s[i][j] * ATT_SCALE : -1e30f;
                rowm = fmaxf(rowm, s[i][j]);
            }
#pragma unroll
            for (int off = 8; off > 0; off >>= 1)
                rowm = fmaxf(rowm, __shfl_xor_sync(0xffffffffu, rowm, off));

            float scaleOld = __expf(m_i[i] - rowm);
            float lsum = 0.f;
#pragma unroll
            for (int j = 0; j < 4; ++j) {
                float p = vld[j] ? __expf(s[i][j] - rowm) : 0.f;
                Ps[ty * 4 + i][tx * 4 + j] = p;
                lsum += p;
            }
#pragma unroll
            for (int off = 8; off > 0; off >>= 1)
                lsum += __shfl_xor_sync(0xffffffffu, lsum, off);

            l_i[i] = l_i[i] * scaleOld + lsum;
            m_i[i] = rowm;
#pragma unroll
            for (int j = 0; j < 4; ++j) o_acc[i][j] *= scaleOld;
        }
        __syncthreads();

#pragma unroll 8
        for (int kk = 0; kk < KT; ++kk) {
            float pv[4], vv[4];
#pragma unroll
            for (int i = 0; i < 4; ++i) pv[i] = Ps[ty * 4 + i][kk];
#pragma unroll
            for (int j = 0; j < 4; ++j) vv[j] = Vs[kk][tx * 4 + j];
#pragma unroll
            for (int i = 0; i < 4; ++i)
#pragma unroll
                for (int j = 0; j < 4; ++j)
                    o_acc[i][j] = fmaf(pv[i], vv[j], o_acc[i][j]);
        }
        __syncthreads();
    }

#pragma unroll
    for (int i = 0; i < 4; ++i) {
        int q = q0 + ty * 4 + i;
        float invl = 1.f / l_i[i];
        float4 v = make_float4(o_acc[i][0] * invl, o_acc[i][1] * invl,
                               o_acc[i][2] * invl, o_acc[i][3] * invl);
        *(float4*)&out[(size_t)(n * TSEQ + q) * DM + h * HD + tx * 4] = v;
    }
}

// ---------------------------------------------------------------------------
extern "C" void kernel_launch(void* const* d_in, const int* in_sizes, int n_in,
                              void* d_out, int out_size)
{
    const float* x    = (const float*)d_in[0];
    const float* wqkv = (const float*)d_in[1];
    const float* outw = (const float*)d_in[2];
    const float* outb = (const float*)d_in[3];
    float* out = (float*)d_out;

    void* qkv_p  = nullptr;
    void* attn_p = nullptr;
    cudaGetSymbolAddress(&qkv_p, g_qkv);
    cudaGetSymbolAddress(&attn_p, g_attn);
    float* qkv  = (float*)qkv_p;
    float* attn = (float*)attn_p;

    cudaFuncSetAttribute(attn_kernel,
                         cudaFuncAttributeMaxDynamicSharedMemorySize, ATTN_SMEM);

    // 1) QKV projection: [8192,1536] = x * Wqkv^T   (HMMA, bf16 3-pass split)
    dim3 g1(C3 / 128, NTOK / 128);
    gemm_mma<<<g1, 256>>>(x, wqkv, qkv, nullptr, NTOK, C3, DM);

    // 2) RoPE
    int rope_threads = NTOK * NH * 32;
    rope_kernel<<<(rope_threads + 255) / 256, 256>>>(qkv);

    // 3) Banded attention
    dim3 g3(TSEQ / QT, NH, NB);
    attn_kernel<<<g3, 256, ATTN_SMEM>>>(qkv, attn);

    // 4) Output projection + bias   (HMMA)
    dim3 g4(DM / 128, NTOK / 128);
    gemm_mma<<<g4, 256>>>(attn, outw, out, outb, NTOK, DM, DM);
}

// round 5
// speedup vs baseline: 1.8597x; 1.2155x over previous
#include <cuda_runtime.h>
#include <cuda_bf16.h>
#include <math.h>
#include <stdint.h>

#define NB 4
#define TSEQ 2048
#define DM 512
#define NH 8
#define HD 64
#define NTOK (NB * TSEQ)      // 8192
#define C3 (3 * DM)           // 1536
#define ATT_SCALE 0.125f

__device__ float g_qkv[NTOK * C3];
__device__ float g_attn[NTOK * DM];

// ---------------------------------------------------------------------------
// mma.sync helpers (base sm_1xx target)
// ---------------------------------------------------------------------------
__device__ __forceinline__ uint32_t smem_u32(const void* p) {
    uint32_t a;
    asm("{ .reg .u64 t; cvta.to.shared.u64 t, %1; cvt.u32.u64 %0, t; }"
        : "=r"(a) : "l"(p));
    return a;
}

#define LDSM_X4(r0, r1, r2, r3, addr)                                      \
    asm volatile("ldmatrix.sync.aligned.m8n8.x4.shared.b16 "               \
                 "{%0,%1,%2,%3}, [%4];"                                    \
                 : "=r"(r0), "=r"(r1), "=r"(r2), "=r"(r3) : "r"(addr))

#define LDSM_X2(r0, r1, addr)                                              \
    asm volatile("ldmatrix.sync.aligned.m8n8.x2.shared.b16 "               \
                 "{%0,%1}, [%2];"                                          \
                 : "=r"(r0), "=r"(r1) : "r"(addr))

#define MMA_BF16(d, a, b)                                                  \
    asm volatile("mma.sync.aligned.m16n8k16.row.col.f32.bf16.bf16.f32 "    \
                 "{%0,%1,%2,%3}, {%4,%5,%6,%7}, {%8,%9}, {%0,%1,%2,%3};"   \
                 : "+f"((d)[0]), "+f"((d)[1]), "+f"((d)[2]), "+f"((d)[3])  \
                 : "r"((a)[0]), "r"((a)[1]), "r"((a)[2]), "r"((a)[3]),     \
                   "r"((b)[0]), "r"((b)[1]))

__device__ __forceinline__ uint32_t pack_hi(float x, float y) {
    __nv_bfloat162 t;
    t.x = __float2bfloat16(x);
    t.y = __float2bfloat16(y);
    return *reinterpret_cast<uint32_t*>(&t);
}
__device__ __forceinline__ uint32_t pack_lo(float x, float y) {
    __nv_bfloat162 t;
    t.x = __float2bfloat16(x - __bfloat162float(__float2bfloat16(x)));
    t.y = __float2bfloat16(y - __bfloat162float(__float2bfloat16(y)));
    return *reinterpret_cast<uint32_t*>(&t);
}

// ---------------------------------------------------------------------------
// HMMA GEMM (unchanged from R4 passing version)
// ---------------------------------------------------------------------------
#define KC 32
#define LDP 40
#define LDPB (LDP * 2)

__global__ void __launch_bounds__(256) gemm_mma(
    const float* __restrict__ A, const float* __restrict__ B,
    float* __restrict__ C, const float* __restrict__ bias,
    int M, int N, int K)
{
    __shared__ __nv_bfloat16 Ah[128 * LDP], Al[128 * LDP];
    __shared__ __nv_bfloat16 Bh[128 * LDP], Bl[128 * LDP];

    const int tid  = threadIdx.x;
    const int wid  = tid >> 5;
    const int lane = tid & 31;
    const int wm   = wid >> 2;
    const int wn   = wid & 3;
    const int mBase = blockIdx.y << 7;
    const int nBase = blockIdx.x << 7;

    const uint32_t baseAh = smem_u32(Ah), baseAl = smem_u32(Al);
    const uint32_t baseBh = smem_u32(Bh), baseBl = smem_u32(Bl);

    const uint32_t aOff = (uint32_t)((wm * 64 + (lane & 15)) * LDPB
                                     + (lane >> 4) * 16);
    const uint32_t bOff = (uint32_t)((wn * 32 + (lane & 7)) * LDPB
                                     + ((lane >> 3) & 1) * 16);

    float acc[4][4][4];
#pragma unroll
    for (int i = 0; i < 4; ++i)
#pragma unroll
        for (int j = 0; j < 4; ++j)
#pragma unroll
            for (int r = 0; r < 4; ++r) acc[i][j][r] = 0.f;

    const int nchunk = K / KC;
    for (int ch = 0; ch < nchunk; ++ch) {
        const int k0 = ch * KC;
        __syncthreads();
#pragma unroll
        for (int it = 0; it < 4; ++it) {
            int idx = it * 256 + tid;
            int row = idx >> 3;
            int f4  = idx & 7;
            int so  = row * LDP + f4 * 4;
            float4 a = *(const float4*)&A[(size_t)(mBase + row) * K + k0 + f4 * 4];
            *(uint2*)&Ah[so] = make_uint2(pack_hi(a.x, a.y), pack_hi(a.z, a.w));
            *(uint2*)&Al[so] = make_uint2(pack_lo(a.x, a.y), pack_lo(a.z, a.w));
            float4 b = *(const float4*)&B[(size_t)(nBase + row) * K + k0 + f4 * 4];
            *(uint2*)&Bh[so] = make_uint2(pack_hi(b.x, b.y), pack_hi(b.z, b.w));
            *(uint2*)&Bl[so] = make_uint2(pack_lo(b.x, b.y), pack_lo(b.z, b.w));
        }
        __syncthreads();

#pragma unroll
        for (int ks = 0; ks < 2; ++ks) {
            const uint32_t kb = (uint32_t)(ks * 32);
            uint32_t ah[4][4], al[4][4], bh[4][2], bl[4][2];
#pragma unroll
            for (int mt = 0; mt < 4; ++mt) {
                uint32_t ad = aOff + (uint32_t)(mt * 16 * LDPB) + kb;
                LDSM_X4(ah[mt][0], ah[mt][1], ah[mt][2], ah[mt][3], baseAh + ad);
                LDSM_X4(al[mt][0], al[mt][1], al[mt][2], al[mt][3], baseAl + ad);
            }
#pragma unroll
            for (int nt = 0; nt < 4; ++nt) {
                uint32_t bd = bOff + (uint32_t)(nt * 8 * LDPB) + kb;
                LDSM_X2(bh[nt][0], bh[nt][1], baseBh + bd);
                LDSM_X2(bl[nt][0], bl[nt][1], baseBl + bd);
            }
#pragma unroll
            for (int mt = 0; mt < 4; ++mt)
#pragma unroll
                for (int nt = 0; nt < 4; ++nt) {
                    MMA_BF16(acc[mt][nt], ah[mt], bh[nt]);
                    MMA_BF16(acc[mt][nt], ah[mt], bl[nt]);
                    MMA_BF16(acc[mt][nt], al[mt], bh[nt]);
                }
        }
    }

    const int er = lane >> 2;
    const int ec = (lane & 3) << 1;
#pragma unroll
    for (int mt = 0; mt < 4; ++mt) {
#pragma unroll
        for (int nt = 0; nt < 4; ++nt) {
            int col = nBase + wn * 32 + nt * 8 + ec;
            float b0 = bias ? bias[col]     : 0.f;
            float b1 = bias ? bias[col + 1] : 0.f;
            int row0 = mBase + wm * 64 + mt * 16 + er;
            float2 v0 = make_float2(acc[mt][nt][0] + b0, acc[mt][nt][1] + b1);
            float2 v1 = make_float2(acc[mt][nt][2] + b0, acc[mt][nt][3] + b1);
            *(float2*)&C[(size_t)row0 * N + col]       = v0;
            *(float2*)&C[(size_t)(row0 + 8) * N + col] = v1;
        }
    }
}

// ---------------------------------------------------------------------------
// RoPE in-place on q,k of g_qkv
// ---------------------------------------------------------------------------
__global__ void rope_kernel(float* __restrict__ qkv)
{
    int idx = blockIdx.x * blockDim.x + threadIdx.x;
    if (idx >= NTOK * NH * 32) return;
    int i  = idx & 31;
    int h  = (idx >> 5) & (NH - 1);
    int nt = idx >> 8;
    int t  = nt & (TSEQ - 1);

    float inv = (float)exp(-(double)i / 32.0 * 9.210340371976184);
    float ang = (float)t * inv;
    float s, c;
    sincosf(ang, &s, &c);

    float* p = qkv + (size_t)nt * C3 + h * HD + i;
    float q1 = p[0], q2 = p[32];
    p[0]  = q1 * c - q2 * s;
    p[32] = q2 * c + q1 * s;
    float* pk = p + DM;
    float k1 = pk[0], k2 = pk[32];
    pk[0]  = k1 * c - k2 * s;
    pk[32] = k2 * c + k1 * s;
}

// ---------------------------------------------------------------------------
// HMMA banded flash attention.
// Block: 64 queries x (head, batch). 4 warps; warp w owns query rows w*16..+15.
// S = Q K^T (3-pass bf16 split), in-register softmax, O += P V (3-pass).
// V stored transposed in smem ([dim][key]) so B-operand pattern matches GEMM.
// ---------------------------------------------------------------------------
#define APAD  72          // bf16 row stride
#define APADB 144         // bytes

__global__ void __launch_bounds__(128) attn_mma(
    const float* __restrict__ qkv, float* __restrict__ out)
{
    __shared__ __nv_bfloat16 Qh[64 * APAD], Ql[64 * APAD];
    __shared__ __nv_bfloat16 Kh[64 * APAD], Kl[64 * APAD];
    __shared__ __nv_bfloat16 Vh[64 * APAD], Vl[64 * APAD];  // transposed

    const int tid  = threadIdx.x;
    const int wid  = tid >> 5;
    const int lane = tid & 31;
    const int qt = blockIdx.x, h = blockIdx.y, n = blockIdx.z;
    const int q0 = qt * 64;
    const int base = n * TSEQ * C3 + h * HD;

    const uint32_t baseQh = smem_u32(Qh), baseQl = smem_u32(Ql);
    const uint32_t baseKh = smem_u32(Kh), baseKl = smem_u32(Kl);
    const uint32_t baseVh = smem_u32(Vh), baseVl = smem_u32(Vl);

    // ---- Load + split Q tile [64 q x 64 d] ----
#pragma unroll
    for (int it = 0; it < 8; ++it) {
        int idx = it * 128 + tid;
        int row = idx >> 4;
        int f4  = idx & 15;
        float4 a = *(const float4*)&qkv[base + (q0 + row) * C3 + f4 * 4];
        int so = row * APAD + f4 * 4;
        *(uint2*)&Qh[so] = make_uint2(pack_hi(a.x, a.y), pack_hi(a.z, a.w));
        *(uint2*)&Ql[so] = make_uint2(pack_lo(a.x, a.y), pack_lo(a.z, a.w));
    }
    __syncthreads();

    // ---- Hoist Q fragments (4 k-tiles over dim) ----
    const uint32_t aOff = (uint32_t)((wid * 16 + (lane & 15)) * APADB
                                     + (lane >> 4) * 16);
    uint32_t qh[4][4], ql[4][4];
#pragma unroll
    for (int kt = 0; kt < 4; ++kt) {
        LDSM_X4(qh[kt][0], qh[kt][1], qh[kt][2], qh[kt][3], baseQh + aOff + kt * 32);
        LDSM_X4(ql[kt][0], ql[kt][1], ql[kt][2], ql[kt][3], baseQl + aOff + kt * 32);
    }

    float m_[2] = {-1e30f, -1e30f};
    float l_[2] = {0.f, 0.f};
    float oacc[8][4];
#pragma unroll
    for (int i = 0; i < 8; ++i)
#pragma unroll
        for (int r = 0; r < 4; ++r) oacc[i][r] = 0.f;

    const int kv_begin = max(0, q0 - 128);
    const int kv_end   = min(TSEQ, q0 + 64 + 128);

    // B-operand ldmatrix address (16 rows x 16 cols per x4)
    const uint32_t bOff = (uint32_t)((lane & 15) * APADB + (lane >> 4) * 16);

    const int rbase = lane >> 2;             // local row within warp tile
    const int cbase = (lane & 3) << 1;       // local col pair base

    for (int kc = kv_begin; kc < kv_end; kc += 64) {
        __syncthreads();
        // ---- Load chunk: K [key][dim] (native), V transposed [dim][key] ----
#pragma unroll
        for (int it = 0; it < 8; ++it) {
            int idx = it * 128 + tid;
            int row = idx >> 4;              // key index
            int f4  = idx & 15;              // float4 along dim
            int roff = base + (kc + row) * C3 + f4 * 4;
            float4 kk = *(const float4*)&qkv[roff + DM];
            int so = row * APAD + f4 * 4;
            *(uint2*)&Kh[so] = make_uint2(pack_hi(kk.x, kk.y), pack_hi(kk.z, kk.w));
            *(uint2*)&Kl[so] = make_uint2(pack_lo(kk.x, kk.y), pack_lo(kk.z, kk.w));
            float4 vv = *(const float4*)&qkv[roff + 2 * DM];
            int d0 = f4 * 4;
            Vh[(d0 + 0) * APAD + row] = __float2bfloat16(vv.x);
            Vl[(d0 + 0) * APAD + row] = __float2bfloat16(vv.x - __bfloat162float(__float2bfloat16(vv.x)));
            Vh[(d0 + 1) * APAD + row] = __float2bfloat16(vv.y);
            Vl[(d0 + 1) * APAD + row] = __float2bfloat16(vv.y - __bfloat162float(__float2bfloat16(vv.y)));
            Vh[(d0 + 2) * APAD + row] = __float2bfloat16(vv.z);
            Vl[(d0 + 2) * APAD + row] = __float2bfloat16(vv.z - __bfloat162float(__float2bfloat16(vv.z)));
            Vh[(d0 + 3) * APAD + row] = __float2bfloat16(vv.w);
            Vl[(d0 + 3) * APAD + row] = __float2bfloat16(vv.w - __bfloat162float(__float2bfloat16(vv.w)));
        }
        __syncthreads();

        // ---- S = Q K^T (8 n-tiles of 8 keys; 3-pass split) ----
        float sacc[8][4];
#pragma unroll
        for (int i = 0; i < 8; ++i)
#pragma unroll
            for (int r = 0; r < 4; ++r) sacc[i][r] = 0.f;

#pragma unroll
        for (int ntp = 0; ntp < 4; ++ntp) {      // pairs of n-tiles (16 keys)
#pragma unroll
            for (int kt = 0; kt < 4; ++kt) {
                uint32_t ad = bOff + (uint32_t)(ntp * 16 * APADB) + (uint32_t)(kt * 32);
                uint32_t r0, r1, r2, r3, s0, s1, s2, s3;
                LDSM_X4(r0, r1, r2, r3, baseKh + ad);
                LDSM_X4(s0, s1, s2, s3, baseKl + ad);
                uint32_t bh0[2] = {r0, r2}, bh1[2] = {r1, r3};
                uint32_t bl0[2] = {s0, s2}, bl1[2] = {s1, s3};
                MMA_BF16(sacc[2 * ntp],     qh[kt], bh0);
                MMA_BF16(sacc[2 * ntp],     qh[kt], bl0);
                MMA_BF16(sacc[2 * ntp],     ql[kt], bh0);
                MMA_BF16(sacc[2 * ntp + 1], qh[kt], bh1);
                MMA_BF16(sacc[2 * ntp + 1], qh[kt], bl1);
                MMA_BF16(sacc[2 * ntp + 1], ql[kt], bh1);
            }
        }

        // ---- mask + scale + row max ----
        float mnew[2] = {m_[0], m_[1]};
#pragma unroll
        for (int nt = 0; nt < 8; ++nt) {
            int key0 = kc + nt * 8 + cbase;
#pragma unroll
            for (int half = 0; half < 2; ++half) {
                int q = q0 + wid * 16 + rbase + half * 8;
#pragma unroll
                for (int c = 0; c < 2; ++c) {
                    int diff = key0 + c - q;
                    bool vld = (diff >= -127) && (diff <= 128);
                    float sv = vld ? sacc[nt][half * 2 + c] * ATT_SCALE : -1e30f;
                    sacc[nt][half * 2 + c] = sv;
                    mnew[half] = fmaxf(mnew[half], sv);
                }
            }
        }
#pragma unroll
        for (int off = 1; off <= 2; off <<= 1) {
            mnew[0] = fmaxf(mnew[0], __shfl_xor_sync(0xffffffffu, mnew[0], off));
            mnew[1] = fmaxf(mnew[1], __shfl_xor_sync(0xffffffffu, mnew[1], off));
        }

        float sc0 = __expf(m_[0] - mnew[0]);
        float sc1 = __expf(m_[1] - mnew[1]);
        float ls[2] = {0.f, 0.f};

        // ---- P = exp(S - m), pack to A fragments (hi/lo) in registers ----
        uint32_t phi[4][4], plo[4][4];
#pragma unroll
        for (int kt = 0; kt < 4; ++kt) {
            int je = 2 * kt, jo = 2 * kt + 1;
            float p0 = __expf(sacc[je][0] - mnew[0]);
            float p1 = __expf(sacc[je][1] - mnew[0]);
            float p2 = __expf(sacc[je][2] - mnew[1]);
            float p3 = __expf(sacc[je][3] - mnew[1]);
            float p4 = __expf(sacc[jo][0] - mnew[0]);
            float p5 = __expf(sacc[jo][1] - mnew[0]);
            float p6 = __expf(sacc[jo][2] - mnew[1]);
            float p7 = __expf(sacc[jo][3] - mnew[1]);
            ls[0] += p0 + p1 + p4 + p5;
            ls[1] += p2 + p3 + p6 + p7;
            phi[kt][0] = pack_hi(p0, p1); plo[kt][0] = pack_lo(p0, p1);
            phi[kt][1] = pack_hi(p2, p3); plo[kt][1] = pack_lo(p2, p3);
            phi[kt][2] = pack_hi(p4, p5); plo[kt][2] = pack_lo(p4, p5);
            phi[kt][3] = pack_hi(p6, p7); plo[kt][3] = pack_lo(p6, p7);
        }
#pragma unroll
        for (int off = 1; off <= 2; off <<= 1) {
            ls[0] += __shfl_xor_sync(0xffffffffu, ls[0], off);
            ls[1] += __shfl_xor_sync(0xffffffffu, ls[1], off);
        }
        l_[0] = l_[0] * sc0 + ls[0];
        l_[1] = l_[1] * sc1 + ls[1];
        m_[0] = mnew[0];
        m_[1] = mnew[1];

#pragma unroll
        for (int nt = 0; nt < 8; ++nt) {
            oacc[nt][0] *= sc0; oacc[nt][1] *= sc0;
            oacc[nt][2] *= sc1; oacc[nt][3] *= sc1;
        }

        // ---- O += P V  (8 dim n-tiles; 3-pass split) ----
#pragma unroll
        for (int ntp = 0; ntp < 4; ++ntp) {      // pairs of dim tiles
#pragma unroll
            for (int kt = 0; kt < 4; ++kt) {     // key k-tiles
                uint32_t ad = bOff + (uint32_t)(ntp * 16 * APADB) + (uint32_t)(kt * 32);
                uint32_t r0, r1, r2, r3, s0, s1, s2, s3;
                LDSM_X4(r0, r1, r2, r3, baseVh + ad);
                LDSM_X4(s0, s1, s2, s3, baseVl + ad);
                uint32_t bh0[2] = {r0, r2}, bh1[2] = {r1, r3};
                uint32_t bl0[2] = {s0, s2}, bl1[2] = {s1, s3};
                MMA_BF16(oacc[2 * ntp],     phi[kt], bh0);
                MMA_BF16(oacc[2 * ntp],     phi[kt], bl0);
                MMA_BF16(oacc[2 * ntp],     plo[kt], bh0);
                MMA_BF16(oacc[2 * ntp + 1], phi[kt], bh1);
                MMA_BF16(oacc[2 * ntp + 1], phi[kt], bl1);
                MMA_BF16(oacc[2 * ntp + 1], plo[kt], bh1);
            }
        }
    }

    // ---- Epilogue: O /= l, write [tok][h*64+d] ----
    float inv0 = 1.f / l_[0];
    float inv1 = 1.f / l_[1];
    int q = q0 + wid * 16 + rbase;
#pragma unroll
    for (int nt = 0; nt < 8; ++nt) {
        int d = nt * 8 + cbase;
        *(float2*)&out[(size_t)(n * TSEQ + q) * DM + h * HD + d] =
            make_float2(oacc[nt][0] * inv0, oacc[nt][1] * inv0);
        *(float2*)&out[(size_t)(n * TSEQ + q + 8) * DM + h * HD + d] =
            make_float2(oacc[nt][2] * inv1, oacc[nt][3] * inv1);
    }
}

// ---------------------------------------------------------------------------
extern "C" void kernel_launch(void* const* d_in, const int* in_sizes, int n_in,
                              void* d_out, int out_size)
{
    const float* x    = (const float*)d_in[0];
    const float* wqkv = (const float*)d_in[1];
    const float* outw = (const float*)d_in[2];
    const float* outb = (const float*)d_in[3];
    float* out = (float*)d_out;

    void* qkv_p  = nullptr;
    void* attn_p = nullptr;
    cudaGetSymbolAddress(&qkv_p, g_qkv);
    cudaGetSymbolAddress(&attn_p, g_attn);
    float* qkv  = (float*)qkv_p;
    float* attn = (float*)attn_p;

    // 1) QKV projection (HMMA)
    dim3 g1(C3 / 128, NTOK / 128);
    gemm_mma<<<g1, 256>>>(x, wqkv, qkv, nullptr, NTOK, C3, DM);

    // 2) RoPE
    int rope_threads = NTOK * NH * 32;
    rope_kernel<<<(rope_threads + 255) / 256, 256>>>(qkv);

    // 3) Banded attention (HMMA)
    dim3 g3(TSEQ / 64, NH, NB);
    attn_mma<<<g3, 128>>>(qkv, attn);

    // 4) Output projection + bias (HMMA)
    dim3 g4(DM / 128, NTOK / 128);
    gemm_mma<<<g4, 256>>>(attn, outw, out, outb, NTOK, DM, DM);
}

// round 6
// speedup vs baseline: 1.9810x; 1.0652x over previous
#include <cuda_runtime.h>
#include <cuda_bf16.h>
#include <math.h>
#include <stdint.h>

#define NB 4
#define TSEQ 2048
#define DM 512
#define NH 8
#define HD 64
#define NTOK (NB * TSEQ)      // 8192
#define C3 (3 * DM)           // 1536
#define ATT_SCALE 0.125f

__device__ float g_qkv[NTOK * C3];
__device__ float g_attn[NTOK * DM];

// ---------------------------------------------------------------------------
// mma.sync / cp.async helpers (base sm_1xx target)
// ---------------------------------------------------------------------------
__device__ __forceinline__ uint32_t smem_u32(const void* p) {
    uint32_t a;
    asm("{ .reg .u64 t; cvta.to.shared.u64 t, %1; cvt.u32.u64 %0, t; }"
        : "=r"(a) : "l"(p));
    return a;
}

#define LDSM_X4(r0, r1, r2, r3, addr)                                      \
    asm volatile("ldmatrix.sync.aligned.m8n8.x4.shared.b16 "               \
                 "{%0,%1,%2,%3}, [%4];"                                    \
                 : "=r"(r0), "=r"(r1), "=r"(r2), "=r"(r3) : "r"(addr))

#define LDSM_X4_T(r0, r1, r2, r3, addr)                                    \
    asm volatile("ldmatrix.sync.aligned.m8n8.x4.trans.shared.b16 "         \
                 "{%0,%1,%2,%3}, [%4];"                                    \
                 : "=r"(r0), "=r"(r1), "=r"(r2), "=r"(r3) : "r"(addr))

#define MMA_BF16(d, a, b)                                                  \
    asm volatile("mma.sync.aligned.m16n8k16.row.col.f32.bf16.bf16.f32 "    \
                 "{%0,%1,%2,%3}, {%4,%5,%6,%7}, {%8,%9}, {%0,%1,%2,%3};"   \
                 : "+f"((d)[0]), "+f"((d)[1]), "+f"((d)[2]), "+f"((d)[3])  \
                 : "r"((a)[0]), "r"((a)[1]), "r"((a)[2]), "r"((a)[3]),     \
                   "r"((b)[0]), "r"((b)[1]))

#define CP_ASYNC16(saddr, gptr)                                            \
    asm volatile("cp.async.cg.shared.global [%0], [%1], 16;"               \
                 :: "r"(saddr), "l"(gptr) : "memory")
#define CP_COMMIT() asm volatile("cp.async.commit_group;" ::: "memory")

__device__ __forceinline__ uint32_t pack_hi(float x, float y) {
    __nv_bfloat162 t;
    t.x = __float2bfloat16(x);
    t.y = __float2bfloat16(y);
    return *reinterpret_cast<uint32_t*>(&t);
}
__device__ __forceinline__ uint32_t pack_lo(float x, float y) {
    __nv_bfloat162 t;
    t.x = __float2bfloat16(x - __bfloat162float(__float2bfloat16(x)));
    t.y = __float2bfloat16(y - __bfloat162float(__float2bfloat16(y)));
    return *reinterpret_cast<uint32_t*>(&t);
}

// ---------------------------------------------------------------------------
// HMMA GEMM with cp.async double-buffered fp32 staging.
// C[M,N] = A[M,K] B[N,K]^T (+bias). Tile 128x128, K-chunk 32, 3-pass bf16 split.
// ---------------------------------------------------------------------------
#define KC 32
#define LDP 40
#define LDPB 80
#define GEMM_BF16_BYTES (4 * 128 * LDP * 2)                 // 40960
#define GEMM_SMEM_TOTAL (GEMM_BF16_BYTES + 2 * 2 * 128 * 32 * 4)  // 106496

__global__ void __launch_bounds__(256, 2) gemm_mma(
    const float* __restrict__ A, const float* __restrict__ B,
    float* __restrict__ C, const float* __restrict__ bias,
    int M, int N, int K)
{
    extern __shared__ char dsm[];
    __nv_bfloat16* Ah = (__nv_bfloat16*)dsm;
    __nv_bfloat16* Al = Ah + 128 * LDP;
    __nv_bfloat16* Bh = Al + 128 * LDP;
    __nv_bfloat16* Bl = Bh + 128 * LDP;
    float* stg = (float*)(dsm + GEMM_BF16_BYTES);   // [2 buf][A|B][128*32]

    const int tid  = threadIdx.x;
    const int wid  = tid >> 5;
    const int lane = tid & 31;
    const int wm   = wid >> 2;
    const int wn   = wid & 3;
    const int mBase = blockIdx.y << 7;
    const int nBase = blockIdx.x << 7;

    const uint32_t baseAh = smem_u32(Ah), baseAl = smem_u32(Al);
    const uint32_t baseBh = smem_u32(Bh), baseBl = smem_u32(Bl);
    const uint32_t stgAddr = smem_u32(stg);

    const int r0w = tid >> 3;     // staged row base (advances by 32 per it)
    const int f4  = tid & 7;      // float4 slot along K

    const float* Ap = A + (size_t)mBase * K;
    const float* Bp = B + (size_t)nBase * K;

    const uint32_t aOff = (uint32_t)((wm * 64 + (lane & 15)) * LDPB
                                     + (lane >> 4) * 16);
    const uint32_t bOff = (uint32_t)((wn * 32 + (lane & 15)) * LDPB
                                     + (lane >> 4) * 16);

    float acc[4][4][4];
#pragma unroll
    for (int i = 0; i < 4; ++i)
#pragma unroll
        for (int j = 0; j < 4; ++j)
#pragma unroll
            for (int r = 0; r < 4; ++r) acc[i][j][r] = 0.f;

    const int nchunk = K / KC;

    // ---- stage chunk 0 ----
    {
        uint32_t sA = stgAddr;
        uint32_t sB = stgAddr + 4096 * 4;
#pragma unroll
        for (int it = 0; it < 4; ++it) {
            int row = it * 32 + r0w;
            uint32_t off = (uint32_t)((row * 32 + f4 * 4) * 4);
            CP_ASYNC16(sA + off, Ap + (size_t)row * K + f4 * 4);
            CP_ASYNC16(sB + off, Bp + (size_t)row * K + f4 * 4);
        }
        CP_COMMIT();
    }

    for (int ch = 0; ch < nchunk; ++ch) {
        const int buf = ch & 1;
        // issue next chunk, then wait for current
        if (ch + 1 < nchunk) {
            const int k0 = (ch + 1) * KC;
            uint32_t sA = stgAddr + (uint32_t)((buf ^ 1) * 8192 * 4);
            uint32_t sB = sA + 4096 * 4;
#pragma unroll
            for (int it = 0; it < 4; ++it) {
                int row = it * 32 + r0w;
                uint32_t off = (uint32_t)((row * 32 + f4 * 4) * 4);
                CP_ASYNC16(sA + off, Ap + (size_t)row * K + k0 + f4 * 4);
                CP_ASYNC16(sB + off, Bp + (size_t)row * K + k0 + f4 * 4);
            }
            CP_COMMIT();
            asm volatile("cp.async.wait_group 1;" ::: "memory");
        } else {
            asm volatile("cp.async.wait_group 0;" ::: "memory");
        }
        __syncthreads();   // previous MMA phase done before overwriting bf16 bufs

        // ---- convert own staged data -> bf16 hi/lo planes ----
        const float* sA = stg + buf * 8192;
        const float* sB = sA + 4096;
#pragma unroll
        for (int it = 0; it < 4; ++it) {
            int row = it * 32 + r0w;
            int si = row * 32 + f4 * 4;
            int so = row * LDP + f4 * 4;
            float4 a = *(const float4*)&sA[si];
            *(uint2*)&Ah[so] = make_uint2(pack_hi(a.x, a.y), pack_hi(a.z, a.w));
            *(uint2*)&Al[so] = make_uint2(pack_lo(a.x, a.y), pack_lo(a.z, a.w));
            float4 b = *(const float4*)&sB[si];
            *(uint2*)&Bh[so] = make_uint2(pack_hi(b.x, b.y), pack_hi(b.z, b.w));
            *(uint2*)&Bl[so] = make_uint2(pack_lo(b.x, b.y), pack_lo(b.z, b.w));
        }
        __syncthreads();

        // ---- MMA phase ----
#pragma unroll
        for (int ks = 0; ks < 2; ++ks) {
            const uint32_t kb = (uint32_t)(ks * 32);
            uint32_t ah[4][4], al[4][4], bh[4][2], bl[4][2];
#pragma unroll
            for (int mt = 0; mt < 4; ++mt) {
                uint32_t ad = aOff + (uint32_t)(mt * 16 * LDPB) + kb;
                LDSM_X4(ah[mt][0], ah[mt][1], ah[mt][2], ah[mt][3], baseAh + ad);
                LDSM_X4(al[mt][0], al[mt][1], al[mt][2], al[mt][3], baseAl + ad);
            }
#pragma unroll
            for (int ntp = 0; ntp < 2; ++ntp) {
                uint32_t bd = bOff + (uint32_t)(ntp * 16 * LDPB) + kb;
                uint32_t r0, r1, r2, r3;
                LDSM_X4(r0, r1, r2, r3, baseBh + bd);
                bh[2 * ntp][0] = r0; bh[2 * ntp][1] = r2;
                bh[2 * ntp + 1][0] = r1; bh[2 * ntp + 1][1] = r3;
                LDSM_X4(r0, r1, r2, r3, baseBl + bd);
                bl[2 * ntp][0] = r0; bl[2 * ntp][1] = r2;
                bl[2 * ntp + 1][0] = r1; bl[2 * ntp + 1][1] = r3;
            }
#pragma unroll
            for (int mt = 0; mt < 4; ++mt)
#pragma unroll
                for (int nt = 0; nt < 4; ++nt) {
                    MMA_BF16(acc[mt][nt], ah[mt], bh[nt]);
                    MMA_BF16(acc[mt][nt], ah[mt], bl[nt]);
                    MMA_BF16(acc[mt][nt], al[mt], bh[nt]);
                }
        }
    }

    const int er = lane >> 2;
    const int ec = (lane & 3) << 1;
#pragma unroll
    for (int mt = 0; mt < 4; ++mt) {
#pragma unroll
        for (int nt = 0; nt < 4; ++nt) {
            int col = nBase + wn * 32 + nt * 8 + ec;
            float b0 = bias ? bias[col]     : 0.f;
            float b1 = bias ? bias[col + 1] : 0.f;
            int row0 = mBase + wm * 64 + mt * 16 + er;
            float2 v0 = make_float2(acc[mt][nt][0] + b0, acc[mt][nt][1] + b1);
            float2 v1 = make_float2(acc[mt][nt][2] + b0, acc[mt][nt][3] + b1);
            *(float2*)&C[(size_t)row0 * N + col]       = v0;
            *(float2*)&C[(size_t)(row0 + 8) * N + col] = v1;
        }
    }
}

// ---------------------------------------------------------------------------
// RoPE in-place on q,k of g_qkv
// ---------------------------------------------------------------------------
__global__ void rope_kernel(float* __restrict__ qkv)
{
    int idx = blockIdx.x * blockDim.x + threadIdx.x;
    if (idx >= NTOK * NH * 32) return;
    int i  = idx & 31;
    int h  = (idx >> 5) & (NH - 1);
    int nt = idx >> 8;
    int t  = nt & (TSEQ - 1);

    float inv = (float)exp(-(double)i / 32.0 * 9.210340371976184);
    float ang = (float)t * inv;
    float s, c;
    sincosf(ang, &s, &c);

    float* p = qkv + (size_t)nt * C3 + h * HD + i;
    float q1 = p[0], q2 = p[32];
    p[0]  = q1 * c - q2 * s;
    p[32] = q2 * c + q1 * s;
    float* pk = p + DM;
    float k1 = pk[0], k2 = pk[32];
    pk[0]  = k1 * c - k2 * s;
    pk[32] = k2 * c + k1 * s;
}

// ---------------------------------------------------------------------------
// HMMA banded flash attention. V kept in NATIVE [key][dim] layout;
// PV B-fragments come from ldmatrix.x4.trans (no scalar transpose stores).
// ---------------------------------------------------------------------------
#define APAD  72
#define APADB 144

__global__ void __launch_bounds__(128) attn_mma(
    const float* __restrict__ qkv, float* __restrict__ out)
{
    __shared__ __nv_bfloat16 Qh[64 * APAD], Ql[64 * APAD];
    __shared__ __nv_bfloat16 Kh[64 * APAD], Kl[64 * APAD];
    __shared__ __nv_bfloat16 Vh[64 * APAD], Vl[64 * APAD];  // native [key][dim]

    const int tid  = threadIdx.x;
    const int wid  = tid >> 5;
    const int lane = tid & 31;
    const int qt = blockIdx.x, h = blockIdx.y, n = blockIdx.z;
    const int q0 = qt * 64;
    const int base = n * TSEQ * C3 + h * HD;

    const uint32_t baseQh = smem_u32(Qh), baseQl = smem_u32(Ql);
    const uint32_t baseKh = smem_u32(Kh), baseKl = smem_u32(Kl);
    const uint32_t baseVh = smem_u32(Vh), baseVl = smem_u32(Vl);

    // ---- Load + split Q tile [64 q x 64 d] ----
#pragma unroll
    for (int it = 0; it < 8; ++it) {
        int idx = it * 128 + tid;
        int row = idx >> 4;
        int f4  = idx & 15;
        float4 a = *(const float4*)&qkv[base + (q0 + row) * C3 + f4 * 4];
        int so = row * APAD + f4 * 4;
        *(uint2*)&Qh[so] = make_uint2(pack_hi(a.x, a.y), pack_hi(a.z, a.w));
        *(uint2*)&Ql[so] = make_uint2(pack_lo(a.x, a.y), pack_lo(a.z, a.w));
    }
    __syncthreads();

    // ---- Hoist Q fragments ----
    const uint32_t aOff = (uint32_t)((wid * 16 + (lane & 15)) * APADB
                                     + (lane >> 4) * 16);
    uint32_t qh[4][4], ql[4][4];
#pragma unroll
    for (int kt = 0; kt < 4; ++kt) {
        LDSM_X4(qh[kt][0], qh[kt][1], qh[kt][2], qh[kt][3], baseQh + aOff + kt * 32);
        LDSM_X4(ql[kt][0], ql[kt][1], ql[kt][2], ql[kt][3], baseQl + aOff + kt * 32);
    }

    float m_[2] = {-1e30f, -1e30f};
    float l_[2] = {0.f, 0.f};
    float oacc[8][4];
#pragma unroll
    for (int i = 0; i < 8; ++i)
#pragma unroll
        for (int r = 0; r < 4; ++r) oacc[i][r] = 0.f;

    const int kv_begin = max(0, q0 - 128);
    const int kv_end   = min(TSEQ, q0 + 64 + 128);

    const uint32_t bOff = (uint32_t)((lane & 15) * APADB + (lane >> 4) * 16);
    const int rbase = lane >> 2;
    const int cbase = (lane & 3) << 1;

    for (int kc = kv_begin; kc < kv_end; kc += 64) {
        __syncthreads();
        // ---- Load chunk: K and V both native [key][dim], vectorized ----
#pragma unroll
        for (int it = 0; it < 8; ++it) {
            int idx = it * 128 + tid;
            int row = idx >> 4;
            int f4  = idx & 15;
            int roff = base + (kc + row) * C3 + f4 * 4;
            int so = row * APAD + f4 * 4;
            float4 kk = *(const float4*)&qkv[roff + DM];
            *(uint2*)&Kh[so] = make_uint2(pack_hi(kk.x, kk.y), pack_hi(kk.z, kk.w));
            *(uint2*)&Kl[so] = make_uint2(pack_lo(kk.x, kk.y), pack_lo(kk.z, kk.w));
            float4 vv = *(const float4*)&qkv[roff + 2 * DM];
            *(uint2*)&Vh[so] = make_uint2(pack_hi(vv.x, vv.y), pack_hi(vv.z, vv.w));
            *(uint2*)&Vl[so] = make_uint2(pack_lo(vv.x, vv.y), pack_lo(vv.z, vv.w));
        }
        __syncthreads();

        // ---- S = Q K^T ----
        float sacc[8][4];
#pragma unroll
        for (int i = 0; i < 8; ++i)
#pragma unroll
            for (int r = 0; r < 4; ++r) sacc[i][r] = 0.f;

#pragma unroll
        for (int ntp = 0; ntp < 4; ++ntp) {
#pragma unroll
            for (int kt = 0; kt < 4; ++kt) {
                uint32_t ad = bOff + (uint32_t)(ntp * 16 * APADB) + (uint32_t)(kt * 32);
                uint32_t r0, r1, r2, r3, s0, s1, s2, s3;
                LDSM_X4(r0, r1, r2, r3, baseKh + ad);
                LDSM_X4(s0, s1, s2, s3, baseKl + ad);
                uint32_t bh0[2] = {r0, r2}, bh1[2] = {r1, r3};
                uint32_t bl0[2] = {s0, s2}, bl1[2] = {s1, s3};
                MMA_BF16(sacc[2 * ntp],     qh[kt], bh0);
                MMA_BF16(sacc[2 * ntp],     qh[kt], bl0);
                MMA_BF16(sacc[2 * ntp],     ql[kt], bh0);
                MMA_BF16(sacc[2 * ntp + 1], qh[kt], bh1);
                MMA_BF16(sacc[2 * ntp + 1], qh[kt], bl1);
                MMA_BF16(sacc[2 * ntp + 1], ql[kt], bh1);
            }
        }

        // ---- mask + scale + row max ----
        float mnew[2] = {m_[0], m_[1]};
#pragma unroll
        for (int nt = 0; nt < 8; ++nt) {
            int key0 = kc + nt * 8 + cbase;
#pragma unroll
            for (int half = 0; half < 2; ++half) {
                int q = q0 + wid * 16 + rbase + half * 8;
#pragma unroll
                for (int c = 0; c < 2; ++c) {
                    int diff = key0 + c - q;
                    bool vld = (diff >= -127) && (diff <= 128);
                    float sv = vld ? sacc[nt][half * 2 + c] * ATT_SCALE : -1e30f;
                    sacc[nt][half * 2 + c] = sv;
                    mnew[half] = fmaxf(mnew[half], sv);
                }
            }
        }
#pragma unroll
        for (int off = 1; off <= 2; off <<= 1) {
            mnew[0] = fmaxf(mnew[0], __shfl_xor_sync(0xffffffffu, mnew[0], off));
            mnew[1] = fmaxf(mnew[1], __shfl_xor_sync(0xffffffffu, mnew[1], off));
        }

        float sc0 = __expf(m_[0] - mnew[0]);
        float sc1 = __expf(m_[1] - mnew[1]);
        float ls[2] = {0.f, 0.f};

        // ---- P = exp(S - m), pack to A fragments in registers ----
        uint32_t phi[4][4], plo[4][4];
#pragma unroll
        for (int kt = 0; kt < 4; ++kt) {
            int je = 2 * kt, jo = 2 * kt + 1;
            float p0 = __expf(sacc[je][0] - mnew[0]);
            float p1 = __expf(sacc[je][1] - mnew[0]);
            float p2 = __expf(sacc[je][2] - mnew[1]);
            float p3 = __expf(sacc[je][3] - mnew[1]);
            float p4 = __expf(sacc[jo][0] - mnew[0]);
            float p5 = __expf(sacc[jo][1] - mnew[0]);
            float p6 = __expf(sacc[jo][2] - mnew[1]);
            float p7 = __expf(sacc[jo][3] - mnew[1]);
            ls[0] += p0 + p1 + p4 + p5;
            ls[1] += p2 + p3 + p6 + p7;
            phi[kt][0] = pack_hi(p0, p1); plo[kt][0] = pack_lo(p0, p1);
            phi[kt][1] = pack_hi(p2, p3); plo[kt][1] = pack_lo(p2, p3);
            phi[kt][2] = pack_hi(p4, p5); plo[kt][2] = pack_lo(p4, p5);
            phi[kt][3] = pack_hi(p6, p7); plo[kt][3] = pack_lo(p6, p7);
        }
#pragma unroll
        for (int off = 1; off <= 2; off <<= 1) {
            ls[0] += __shfl_xor_sync(0xffffffffu, ls[0], off);
            ls[1] += __shfl_xor_sync(0xffffffffu, ls[1], off);
        }
        l_[0] = l_[0] * sc0 + ls[0];
        l_[1] = l_[1] * sc1 + ls[1];
        m_[0] = mnew[0];
        m_[1] = mnew[1];

#pragma unroll
        for (int nt = 0; nt < 8; ++nt) {
            oacc[nt][0] *= sc0; oacc[nt][1] *= sc0;
            oacc[nt][2] *= sc1; oacc[nt][3] *= sc1;
        }

        // ---- O += P V  (V native, trans ldmatrix) ----
#pragma unroll
        for (int ntp = 0; ntp < 4; ++ntp) {      // dim-tile pairs
#pragma unroll
            for (int kt = 0; kt < 4; ++kt) {     // key k-tiles
                uint32_t ad = bOff + (uint32_t)(kt * 16 * APADB) + (uint32_t)(ntp * 32);
                uint32_t r0, r1, r2, r3, s0, s1, s2, s3;
                LDSM_X4_T(r0, r1, r2, r3, baseVh + ad);
                LDSM_X4_T(s0, s1, s2, s3, baseVl + ad);
                uint32_t bh0[2] = {r0, r1}, bh1[2] = {r2, r3};
                uint32_t bl0[2] = {s0, s1}, bl1[2] = {s2, s3};
                MMA_BF16(oacc[2 * ntp],     phi[kt], bh0);
                MMA_BF16(oacc[2 * ntp],     phi[kt], bl0);
                MMA_BF16(oacc[2 * ntp],     plo[kt], bh0);
                MMA_BF16(oacc[2 * ntp + 1], phi[kt], bh1);
                MMA_BF16(oacc[2 * ntp + 1], phi[kt], bl1);
                MMA_BF16(oacc[2 * ntp + 1], plo[kt], bh1);
            }
        }
    }

    // ---- Epilogue ----
    float inv0 = 1.f / l_[0];
    float inv1 = 1.f / l_[1];
    int q = q0 + wid * 16 + rbase;
#pragma unroll
    for (int nt = 0; nt < 8; ++nt) {
        int d = nt * 8 + cbase;
        *(float2*)&out[(size_t)(n * TSEQ + q) * DM + h * HD + d] =
            make_float2(oacc[nt][0] * inv0, oacc[nt][1] * inv0);
        *(float2*)&out[(size_t)(n * TSEQ + q + 8) * DM + h * HD + d] =
            make_float2(oacc[nt][2] * inv1, oacc[nt][3] * inv1);
    }
}

// ---------------------------------------------------------------------------
extern "C" void kernel_launch(void* const* d_in, const int* in_sizes, int n_in,
                              void* d_out, int out_size)
{
    const float* x    = (const float*)d_in[0];
    const float* wqkv = (const float*)d_in[1];
    const float* outw = (const float*)d_in[2];
    const float* outb = (const float*)d_in[3];
    float* out = (float*)d_out;

    void* qkv_p  = nullptr;
    void* attn_p = nullptr;
    cudaGetSymbolAddress(&qkv_p, g_qkv);
    cudaGetSymbolAddress(&attn_p, g_attn);
    float* qkv  = (float*)qkv_p;
    float* attn = (float*)attn_p;

    cudaFuncSetAttribute(gemm_mma,
                         cudaFuncAttributeMaxDynamicSharedMemorySize, GEMM_SMEM_TOTAL);

    // 1) QKV projection (HMMA, pipelined)
    dim3 g1(C3 / 128, NTOK / 128);
    gemm_mma<<<g1, 256, GEMM_SMEM_TOTAL>>>(x, wqkv, qkv, nullptr, NTOK, C3, DM);

    // 2) RoPE
    int rope_threads = NTOK * NH * 32;
    rope_kernel<<<(rope_threads + 255) / 256, 256>>>(qkv);

    // 3) Banded attention (HMMA)
    dim3 g3(TSEQ / 64, NH, NB);
    attn_mma<<<g3, 128>>>(qkv, attn);

    // 4) Output projection + bias (HMMA, pipelined)
    dim3 g4(DM / 128, NTOK / 128);
    gemm_mma<<<g4, 256, GEMM_SMEM_TOTAL>>>(attn, outw, out, outb, NTOK, DM, DM);
}